// round 2
// baseline (speedup 1.0000x reference)
#include <cuda_runtime.h>
#include <stdint.h>
#include <math.h>

#define T_   128
#define N1_  256
#define C_   1408
#define K1_  8
#define CN1_ 16
#define N2_  16
#define K2_  3
#define CN2_ 6
#define OT_  22

// ---------------- scratch (static __device__, no runtime allocation) ----------------
static __device__ float g_dist1[(size_t)T_*N1_*N1_];   // 33.5 MB
static __device__ float g_sq1  [T_*N1_];
static __device__ float g_dens1[T_*N1_];
static __device__ int   g_idx1 [T_*N1_];
static __device__ float g_w1   [T_*CN1_];
static __device__ float g_meta1[(size_t)T_*CN1_*C_];   // 11.5 MB
static __device__ float g_dist2[T_*N2_*N2_];
static __device__ float g_dens2[T_*N2_];
static __device__ int   g_idx2 [T_*N2_];
static __device__ float g_w2   [T_*CN2_];
static __device__ float g_meta2[(size_t)T_*CN2_*C_];   // 4.3 MB
static __device__ float g_modu [T_*CN2_];
static __device__ int   g_src  [T_*OT_];
static __device__ int   g_cidv [T_*OT_];

// ---------------- threefry2x32 (exact JAX replica) ----------------
__host__ __device__ __forceinline__ uint32_t rotl32(uint32_t v, int r){ return (v<<r)|(v>>(32-r)); }

__host__ __device__ __forceinline__ void threefry2x32(uint32_t ks0, uint32_t ks1,
                                                      uint32_t x0, uint32_t x1,
                                                      uint32_t& o0, uint32_t& o1){
  uint32_t ks2 = ks0 ^ ks1 ^ 0x1BD11BDAu;
  x0 += ks0; x1 += ks1;
  x0+=x1; x1=rotl32(x1,13); x1^=x0;
  x0+=x1; x1=rotl32(x1,15); x1^=x0;
  x0+=x1; x1=rotl32(x1,26); x1^=x0;
  x0+=x1; x1=rotl32(x1, 6); x1^=x0;
  x0+=ks1; x1+=ks2+1u;
  x0+=x1; x1=rotl32(x1,17); x1^=x0;
  x0+=x1; x1=rotl32(x1,29); x1^=x0;
  x0+=x1; x1=rotl32(x1,16); x1^=x0;
  x0+=x1; x1=rotl32(x1,24); x1^=x0;
  x0+=ks2; x1+=ks0+2u;
  x0+=x1; x1=rotl32(x1,13); x1^=x0;
  x0+=x1; x1=rotl32(x1,15); x1^=x0;
  x0+=x1; x1=rotl32(x1,26); x1^=x0;
  x0+=x1; x1=rotl32(x1, 6); x1^=x0;
  x0+=ks0; x1+=ks1+3u;
  x0+=x1; x1=rotl32(x1,17); x1^=x0;
  x0+=x1; x1=rotl32(x1,29); x1^=x0;
  x0+=x1; x1=rotl32(x1,16); x1^=x0;
  x0+=x1; x1=rotl32(x1,24); x1^=x0;
  x0+=ks1; x1+=ks2+4u;
  o0 = x0; o1 = x1;
}

// ---------------- 1) per-row squared norm (mimics jnp.sum(x*x, -1)) ----------------
__global__ void sq_kernel(const float* __restrict__ X){
  int row  = blockIdx.x * 8 + (threadIdx.x >> 5);
  int lane = threadIdx.x & 31;
  const float* xr = X + (size_t)row * C_;
  float s = 0.f;
  for (int c = lane; c < C_; c += 32){
    float v = xr[c];
    s = __fadd_rn(s, __fmul_rn(v, v));
  }
  #pragma unroll
  for (int o = 16; o; o >>= 1) s = __fadd_rn(s, __shfl_down_sync(0xffffffffu, s, o));
  if (lane == 0) g_sq1[row] = s;
}

// ---------------- 2) Gram + distance (layer 1), 128x128 tile SGEMM ----------------
__global__ void __launch_bounds__(256) gram1_kernel(const float* __restrict__ X){
  int t  = blockIdx.y;
  int bi = (blockIdx.x >> 1) << 7;
  int bj = (blockIdx.x &  1) << 7;
  const float* Xb = X + (size_t)t * N1_ * C_;

  __shared__ float As[16][128];
  __shared__ float Bs[16][128];

  int tid = threadIdx.x;
  int tx = tid & 15, ty = tid >> 4;
  int lr0 = tid >> 2;            // 0..63
  int lc  = (tid & 3) << 2;      // 0,4,8,12

  float acc[8][8];
  #pragma unroll
  for (int u = 0; u < 8; u++)
    #pragma unroll
    for (int v = 0; v < 8; v++) acc[u][v] = 0.f;

  for (int k0 = 0; k0 < C_; k0 += 16){
    #pragma unroll
    for (int u = 0; u < 2; u++){
      int r = lr0 + u * 64;
      float4 a = *(const float4*)(Xb + (size_t)(bi + r) * C_ + k0 + lc);
      As[lc+0][r] = a.x; As[lc+1][r] = a.y; As[lc+2][r] = a.z; As[lc+3][r] = a.w;
      float4 b = *(const float4*)(Xb + (size_t)(bj + r) * C_ + k0 + lc);
      Bs[lc+0][r] = b.x; Bs[lc+1][r] = b.y; Bs[lc+2][r] = b.z; Bs[lc+3][r] = b.w;
    }
    __syncthreads();
    #pragma unroll
    for (int k = 0; k < 16; k++){
      float af[8], bf[8];
      #pragma unroll
      for (int u = 0; u < 8; u++) af[u] = As[k][(ty<<3)+u];
      #pragma unroll
      for (int v = 0; v < 8; v++) bf[v] = Bs[k][(tx<<3)+v];
      #pragma unroll
      for (int u = 0; u < 8; u++)
        #pragma unroll
        for (int v = 0; v < 8; v++) acc[u][v] = __fmaf_rn(af[u], bf[v], acc[u][v]);
    }
    __syncthreads();
  }

  float sqi[8], sqj[8];
  #pragma unroll
  for (int u = 0; u < 8; u++){
    sqi[u] = g_sq1[t*N1_ + bi + (ty<<3) + u];
    sqj[u] = g_sq1[t*N1_ + bj + (tx<<3) + u];
  }
  float sqc = __fsqrt_rn((float)C_);
  #pragma unroll
  for (int u = 0; u < 8; u++){
    #pragma unroll
    for (int v = 0; v < 8; v++){
      float s  = __fadd_rn(sqi[u], sqj[v]);
      float d2 = __fsub_rn(s, __fmul_rn(2.0f, acc[u][v]));
      float dd = __fdiv_rn(__fsqrt_rn(fmaxf(d2, 0.0f)), sqc);
      g_dist1[((size_t)(t*N1_) + bi + (ty<<3) + u) * N1_ + bj + (tx<<3) + v] = dd;
    }
  }
}

// ---------------- 3) knn density + exact threefry noise ----------------
template<int N, int K>
__global__ void knn_kernel(uint32_t key0, uint32_t key1){
  int gid = blockIdx.x * blockDim.x + threadIdx.x;
  if (gid >= T_ * N) return;
  const float* dist = (N == N1_) ? g_dist1 : g_dist2;
  float*       dens = (N == N1_) ? g_dens1 : g_dens2;
  const float* row = dist + (size_t)gid * N;

  float bd[K]; int bix[K];
  #pragma unroll
  for (int p = 0; p < K; p++){ bd[p] = 3.4e38f; bix[p] = 0x7fffffff; }

  for (int j = 0; j < N; j++){
    float d = row[j];
    bool ins = (d < bd[K-1]) || (d == bd[K-1] && j < bix[K-1]);
    if (ins){
      float nd = d; int ni = j;
      #pragma unroll
      for (int p = 0; p < K; p++){
        bool lt = (nd < bd[p]) || (nd == bd[p] && ni < bix[p]);
        if (lt){
          float td = bd[p]; bd[p] = nd; nd = td;
          int   ti = bix[p]; bix[p] = ni; ni = ti;
        }
      }
    }
  }
  float s = 0.f;
  #pragma unroll
  for (int p = 0; p < K; p++) s = __fadd_rn(s, __fmul_rn(bd[p], bd[p]));
  float m = __fdiv_rn(s, (float)K);
  float d = expf(-m);

  const int total = T_ * N, half = total / 2;
  uint32_t o0, o1, u;
  if (gid < half){ threefry2x32(key0, key1, (uint32_t)gid,        (uint32_t)(gid + half), o0, o1); u = o0; }
  else           { threefry2x32(key0, key1, (uint32_t)(gid-half), (uint32_t)gid,          o0, o1); u = o1; }
  float uf = __fadd_rn(__uint_as_float((u >> 9) | 0x3f800000u), -1.0f);
  // floats * (1-0) + 0 are exact no-ops in JAX's uniform
  dens[gid] = __fadd_rn(d, __fmul_rn(uf, 1e-6f));
}

// ---------------- 4) parent_dist, score, top-CN centers, assignment, weights ----------------
template<int N, int CN>
__global__ void cluster_kernel(){
  int t = blockIdx.x;
  int i = threadIdx.x;   // blockDim == N
  const float* dist = (N == N1_) ? g_dist1 : g_dist2;
  const float* dens = (N == N1_) ? g_dens1 : g_dens2;
  int*   idxc = (N == N1_) ? g_idx1 : g_idx2;
  float* wout = (N == N1_) ? g_w1   : g_w2;

  __shared__ float sd[N];
  __shared__ float sred[N];
  __shared__ unsigned long long skey[N];
  __shared__ unsigned long long sred64[N];
  __shared__ int sidx[CN];
  __shared__ int scnt[CN];

  const float* D = dist + (size_t)t * N * N;
  sd[i] = dens[t*N + i];
  __syncthreads();

  float di = sd[i];
  float minv = 3.4e38f; bool hasH = false; float rmax = 0.f;
  const float* rowi = D + (size_t)i * N;
  for (int j = 0; j < N; j++){
    float dv = rowi[j];
    rmax = fmaxf(rmax, dv);
    if (sd[j] > di){ hasH = true; minv = fminf(minv, dv); }
  }
  sred[i] = rmax;
  __syncthreads();
  for (int s = N >> 1; s > 0; s >>= 1){
    if (i < s) sred[i] = fmaxf(sred[i], sred[i+s]);
    __syncthreads();
  }
  float dmax = sred[0];
  float parent = hasH ? minv : dmax;
  float score = __fmul_rn(parent, di);   // score >= 0
  skey[i] = ((unsigned long long)__float_as_uint(score) << 32)
          | (unsigned long long)(0xffffffffu - (uint32_t)i);
  __syncthreads();

  // iterative top-CN by (score desc, index asc)  (matches lax.top_k)
  for (int c = 0; c < CN; c++){
    sred64[i] = skey[i];
    __syncthreads();
    for (int s = N >> 1; s > 0; s >>= 1){
      if (i < s && sred64[i+s] > sred64[i]) sred64[i] = sred64[i+s];
      __syncthreads();
    }
    unsigned long long top = sred64[0];
    int widx = (int)(0xffffffffu - (uint32_t)(top & 0xffffffffu));
    if (i == 0) sidx[c] = widx;
    if (i == widx) skey[i] = 0ull;
    __syncthreads();
  }

  // assignment: argmin over centers (first occurrence), then center override
  float bv = D[(size_t)sidx[0] * N + i];
  int bc = 0;
  for (int c = 1; c < CN; c++){
    float v = D[(size_t)sidx[c] * N + i];
    if (v < bv){ bv = v; bc = c; }
  }
  for (int c = 0; c < CN; c++) if (sidx[c] == i) bc = c;

  if (i < CN) scnt[i] = 0;
  __syncthreads();
  atomicAdd(&scnt[bc], 1);
  idxc[t*N + i] = bc;
  __syncthreads();
  if (i < CN) wout[t*CN + i] = __fdiv_rn(1.0f, __fadd_rn((float)scnt[i], 1e-6f));
}

// ---------------- 5) scatter-mean merge (scale-then-sum, token order) ----------------
template<int N, int CN>
__global__ void merge_kernel(const float* __restrict__ X){
  int t  = blockIdx.y;
  int ch = blockIdx.x * 128 + threadIdx.x;
  const float* Xp  = (N == N1_) ? X : g_meta1;
  const int*  idxc = (N == N1_) ? g_idx1 : g_idx2;
  const float* w   = (N == N1_) ? g_w1   : g_w2;
  float*      outp = (N == N1_) ? g_meta1 : g_meta2;

  __shared__ int sidx[N];
  __shared__ float sw[CN];
  __shared__ float acc[CN][128];

  for (int n = threadIdx.x; n < N; n += 128) sidx[n] = idxc[t*N + n];
  if (threadIdx.x < CN) sw[threadIdx.x] = w[t*CN + threadIdx.x];
  for (int c = 0; c < CN; c++) acc[c][threadIdx.x] = 0.f;
  __syncthreads();

  const float* Xb = Xp + (size_t)t * N * C_ + ch;
  for (int n = 0; n < N; n++){
    int c = sidx[n];
    float v = __fmul_rn(Xb[(size_t)n * C_], sw[c]);
    acc[c][threadIdx.x] = __fadd_rn(acc[c][threadIdx.x], v);
  }
  for (int c = 0; c < CN; c++)
    outp[((size_t)t * CN + c) * C_ + ch] = acc[c][threadIdx.x];
}

// ---------------- 6) layer-2 Gram + distance (16x16 per batch) ----------------
__global__ void gram2_kernel(){
  int t = blockIdx.x;
  int tid = threadIdx.x;           // 256 = 16x16
  int i = tid >> 4, j = tid & 15;
  __shared__ float chunk[N2_][89];
  __shared__ float G[N2_][N2_ + 1];
  const float* Mb = g_meta1 + (size_t)t * N2_ * C_;
  float dot = 0.f;
  for (int c0 = 0; c0 < C_; c0 += 88){
    for (int e = tid; e < N2_ * 88; e += 256){
      int r = e / 88, cc = e - r * 88;
      chunk[r][cc] = Mb[(size_t)r * C_ + c0 + cc];
    }
    __syncthreads();
    #pragma unroll 8
    for (int k = 0; k < 88; k++) dot = __fmaf_rn(chunk[i][k], chunk[j][k], dot);
    __syncthreads();
  }
  G[i][j] = dot;
  __syncthreads();
  float s  = __fadd_rn(G[i][i], G[j][j]);
  float d2 = __fsub_rn(s, __fmul_rn(2.0f, dot));
  g_dist2[(t*N2_ + i)*N2_ + j] = __fdiv_rn(__fsqrt_rn(fmaxf(d2, 0.0f)), __fsqrt_rn((float)C_));
}

// ---------------- 7) modulation (softmax) + grouping order ----------------
__global__ void modu_kernel(const float* __restrict__ sw_, const float* __restrict__ sb_){
  int t = blockIdx.x;
  int tid = threadIdx.x;        // 192
  int wp = tid >> 5, lane = tid & 31;
  __shared__ float smean[CN2_];
  if (wp < CN2_){
    const float* row = g_meta2 + ((size_t)t * CN2_ + wp) * C_;
    float s = 0.f;
    for (int c = lane; c < C_; c += 32) s = __fadd_rn(s, row[c]);
    #pragma unroll
    for (int o = 16; o; o >>= 1) s = __fadd_rn(s, __shfl_down_sync(0xffffffffu, s, o));
    if (lane == 0) smean[wp] = __fdiv_rn(s, (float)C_);
  }
  __syncthreads();
  if (tid == 0){
    float logit[CN2_], e[CN2_];
    for (int k = 0; k < CN2_; k++){
      float l = 0.f;
      for (int j = 0; j < CN2_; j++) l = __fmaf_rn(smean[j], sw_[k*CN2_ + j], l);
      logit[k] = __fadd_rn(l, sb_[k]);
    }
    float mx = logit[0];
    for (int k = 1; k < CN2_; k++) mx = fmaxf(mx, logit[k]);
    float ssum = 0.f;
    for (int k = 0; k < CN2_; k++){ e[k] = expf(__fsub_rn(logit[k], mx)); ssum = __fadd_rn(ssum, e[k]); }
    for (int k = 0; k < CN2_; k++) g_modu[t*CN2_ + k] = __fdiv_rn(e[k], ssum);

    // grouping order: sort_key = cid*(K1+2) + pos, K1 = 16 -> *18
    int key[OT_], src[OT_];
    for (int v = 0; v < CN2_; v++){ key[v] = v * 18; src[v] = v; }
    for (int n = 0; n < CN1_; n++){
      key[CN2_ + n] = g_idx2[t*CN1_ + n] * 18 + 1 + n;
      src[CN2_ + n] = CN2_ + n;
    }
    for (int a = 1; a < OT_; a++){
      int ka = key[a], sa = src[a], b = a - 1;
      while (b >= 0 && key[b] > ka){ key[b+1] = key[b]; src[b+1] = src[b]; b--; }
      key[b+1] = ka; src[b+1] = sa;
    }
    for (int p = 0; p < OT_; p++){
      g_src [t*OT_ + p] = src[p];
      g_cidv[t*OT_ + p] = key[p] / 18;
    }
  }
}

// ---------------- 8) emit scaled grouped tokens ----------------
__global__ void emit_kernel(float* __restrict__ out){
  int t  = blockIdx.y;
  int ch = blockIdx.x * 128 + threadIdx.x;
  __shared__ int ssrc[OT_], scid[OT_];
  __shared__ float sm[CN2_];
  if (threadIdx.x < OT_){
    ssrc[threadIdx.x] = g_src [t*OT_ + threadIdx.x];
    scid[threadIdx.x] = g_cidv[t*OT_ + threadIdx.x];
  }
  if (threadIdx.x < CN2_) sm[threadIdx.x] = g_modu[t*CN2_ + threadIdx.x];
  __syncthreads();
  for (int p = 0; p < OT_; p++){
    int s = ssrc[p];
    float v = (s < CN2_) ? g_meta2[((size_t)t*CN2_ + s) * C_ + ch]
                         : g_meta1[((size_t)t*CN1_ + (s - CN2_)) * C_ + ch];
    out[((size_t)t*OT_ + p) * C_ + ch] = __fmul_rn(v, sm[scid[p]]);
  }
}

// ---------------- launch ----------------
extern "C" void kernel_launch(void* const* d_in, const int* in_sizes, int n_in,
                              void* d_out, int out_size){
  (void)in_sizes; (void)n_in; (void)out_size;
  const float* vis = (const float*)d_in[0];
  const float* sw  = (const float*)d_in[1];
  const float* sb  = (const float*)d_in[2];
  float* out = (float*)d_out;

  // jax.random.key(42) -> split(2): lanes (0,2) and (1,3)
  uint32_t a0, b0, a1, b1;
  threefry2x32(0u, 42u, 0u, 2u, a0, b0);
  threefry2x32(0u, 42u, 1u, 3u, a1, b1);
  // nk[0] = (a0, a1), nk[1] = (b0, b1)

  sq_kernel<<<T_*N1_/8, 256>>>(vis);
  gram1_kernel<<<dim3(4, T_), 256>>>(vis);
  knn_kernel<N1_, K1_><<<(T_*N1_)/256, 256>>>(a0, a1);
  cluster_kernel<N1_, CN1_><<<T_, N1_>>>();
  merge_kernel<N1_, CN1_><<<dim3(C_/128, T_), 128>>>(vis);
  gram2_kernel<<<T_, 256>>>();
  knn_kernel<N2_, K2_><<<(T_*N2_)/256, 256>>>(b0, b1);
  cluster_kernel<N2_, CN2_><<<T_, N2_>>>();
  merge_kernel<N2_, CN2_><<<dim3(C_/128, T_), 128>>>(nullptr);
  modu_kernel<<<T_, 192>>>(sw, sb);
  emit_kernel<<<dim3(C_/128, T_), 128>>>(out);
}

// round 4
// speedup vs baseline: 1.0759x; 1.0759x over previous
#include <cuda_runtime.h>
#include <stdint.h>
#include <math.h>

#define T_   128
#define N1_  256
#define C_   1408
#define K1_  8
#define CN1_ 16
#define N2_  16
#define K2_  3
#define CN2_ 6
#define OT_  22

typedef unsigned long long ull;

// ---------------- scratch (static __device__, no runtime allocation) ----------------
static __device__ float g_dist1[(size_t)T_*N1_*N1_];   // 33.5 MB
static __device__ float g_sq1  [T_*N1_];
static __device__ float g_dens1[T_*N1_];
static __device__ int   g_idx1 [T_*N1_];
static __device__ float g_w1   [T_*CN1_];
static __device__ float g_meta1[(size_t)T_*CN1_*C_];   // 11.5 MB
static __device__ float g_dist2[T_*N2_*N2_];
static __device__ float g_dens2[T_*N2_];
static __device__ int   g_idx2 [T_*N2_];
static __device__ float g_w2   [T_*CN2_];
static __device__ float g_meta2[(size_t)T_*CN2_*C_];   // 4.3 MB
static __device__ float g_modu [T_*CN2_];
static __device__ int   g_src  [T_*OT_];
static __device__ int   g_cidv [T_*OT_];

// ---------------- threefry2x32 (exact JAX replica) ----------------
__host__ __device__ __forceinline__ uint32_t rotl32(uint32_t v, int r){ return (v<<r)|(v>>(32-r)); }

__host__ __device__ __forceinline__ void threefry2x32(uint32_t ks0, uint32_t ks1,
                                                      uint32_t x0, uint32_t x1,
                                                      uint32_t& o0, uint32_t& o1){
  uint32_t ks2 = ks0 ^ ks1 ^ 0x1BD11BDAu;
  x0 += ks0; x1 += ks1;
  x0+=x1; x1=rotl32(x1,13); x1^=x0;
  x0+=x1; x1=rotl32(x1,15); x1^=x0;
  x0+=x1; x1=rotl32(x1,26); x1^=x0;
  x0+=x1; x1=rotl32(x1, 6); x1^=x0;
  x0+=ks1; x1+=ks2+1u;
  x0+=x1; x1=rotl32(x1,17); x1^=x0;
  x0+=x1; x1=rotl32(x1,29); x1^=x0;
  x0+=x1; x1=rotl32(x1,16); x1^=x0;
  x0+=x1; x1=rotl32(x1,24); x1^=x0;
  x0+=ks2; x1+=ks0+2u;
  x0+=x1; x1=rotl32(x1,13); x1^=x0;
  x0+=x1; x1=rotl32(x1,15); x1^=x0;
  x0+=x1; x1=rotl32(x1,26); x1^=x0;
  x0+=x1; x1=rotl32(x1, 6); x1^=x0;
  x0+=ks0; x1+=ks1+3u;
  x0+=x1; x1=rotl32(x1,17); x1^=x0;
  x0+=x1; x1=rotl32(x1,29); x1^=x0;
  x0+=x1; x1=rotl32(x1,16); x1^=x0;
  x0+=x1; x1=rotl32(x1,24); x1^=x0;
  x0+=ks1; x1+=ks2+4u;
  o0 = x0; o1 = x1;
}

// packed dual-f32 FMA (SASS: FFMA2) — bitwise identical to two scalar __fmaf_rn
__device__ __forceinline__ ull ffma2(ull a, ull b, ull c){
  ull d;
  asm("fma.rn.f32x2 %0, %1, %2, %3;" : "=l"(d) : "l"(a), "l"(b), "l"(c));
  return d;
}
__device__ __forceinline__ float lo32(ull v){ return __uint_as_float((uint32_t)v); }
__device__ __forceinline__ float hi32(ull v){ return __uint_as_float((uint32_t)(v >> 32)); }

// ---------------- 1) per-row squared norm ----------------
__global__ void sq_kernel(const float* __restrict__ X){
  int row  = blockIdx.x * 8 + (threadIdx.x >> 5);
  int lane = threadIdx.x & 31;
  const float* xr = X + (size_t)row * C_;
  float s = 0.f;
  for (int c = lane; c < C_; c += 32){
    float v = xr[c];
    s = __fadd_rn(s, __fmul_rn(v, v));
  }
  #pragma unroll
  for (int o = 16; o; o >>= 1) s = __fadd_rn(s, __shfl_down_sync(0xffffffffu, s, o));
  if (lane == 0) g_sq1[row] = s;
}

// ---------------- 2) Gram + distance (layer 1), FFMA2 128x128 tiles, symmetric ----------------
// blockIdx.x: 0 -> (bi=0,bj=0)  1 -> (128,128)  2 -> (0,128). Block (128,0) filled by mirror_kernel.
__global__ void __launch_bounds__(256,2) gram1_kernel(const float* __restrict__ X){
  int t  = blockIdx.y;
  int bb = blockIdx.x;
  int bi = (bb == 1) ? 128 : 0;
  int bj = (bb == 0) ? 0   : 128;
  const float* Xb = X + (size_t)t * N1_ * C_;

  __shared__ float AsD[16][256];   // A duplicated: AsD[k][2r]=AsD[k][2r+1]=A[r][k]
  __shared__ float Bs [16][128];

  int tid = threadIdx.x;
  int tx = tid & 15, ty = tid >> 4;
  int lr0 = tid >> 2;            // 0..63
  int lc  = (tid & 3) << 2;      // 0,4,8,12

  ull acc[8][4];
  #pragma unroll
  for (int u = 0; u < 8; u++)
    #pragma unroll
    for (int v = 0; v < 4; v++) acc[u][v] = 0ull;

  for (int k0 = 0; k0 < C_; k0 += 16){
    #pragma unroll
    for (int u = 0; u < 2; u++){
      int r = lr0 + u * 64;
      float4 a = *(const float4*)(Xb + (size_t)(bi + r) * C_ + k0 + lc);
      *(float2*)&AsD[lc+0][2*r] = make_float2(a.x, a.x);
      *(float2*)&AsD[lc+1][2*r] = make_float2(a.y, a.y);
      *(float2*)&AsD[lc+2][2*r] = make_float2(a.z, a.z);
      *(float2*)&AsD[lc+3][2*r] = make_float2(a.w, a.w);
      float4 b = *(const float4*)(Xb + (size_t)(bj + r) * C_ + k0 + lc);
      Bs[lc+0][r] = b.x; Bs[lc+1][r] = b.y; Bs[lc+2][r] = b.z; Bs[lc+3][r] = b.w;
    }
    __syncthreads();
    #pragma unroll
    for (int k = 0; k < 16; k++){
      const ulonglong2* ap = (const ulonglong2*)&AsD[k][ty * 16];
      ulonglong2 a01 = ap[0], a23 = ap[1], a45 = ap[2], a67 = ap[3];
      const ulonglong2* bp = (const ulonglong2*)&Bs[k][tx * 8];
      ulonglong2 b01 = bp[0], b23 = bp[1];
      ull av[8] = {a01.x, a01.y, a23.x, a23.y, a45.x, a45.y, a67.x, a67.y};
      ull bv[4] = {b01.x, b01.y, b23.x, b23.y};
      #pragma unroll
      for (int u = 0; u < 8; u++)
        #pragma unroll
        for (int v = 0; v < 4; v++) acc[u][v] = ffma2(av[u], bv[v], acc[u][v]);
    }
    __syncthreads();
  }

  float sqi[8], sqj[8];
  #pragma unroll
  for (int u = 0; u < 8; u++){
    sqi[u] = g_sq1[t*N1_ + bi + (ty<<3) + u];
    sqj[u] = g_sq1[t*N1_ + bj + (tx<<3) + u];
  }
  float sqc = __fsqrt_rn((float)C_);
  float* Dt = g_dist1 + (size_t)t * N1_ * N1_;
  #pragma unroll
  for (int u = 0; u < 8; u++){
    int row = bi + (ty<<3) + u;
    #pragma unroll
    for (int v2 = 0; v2 < 4; v2++){
      int c0 = bj + (tx<<3) + 2*v2;
      float g0 = lo32(acc[u][v2]), g1 = hi32(acc[u][v2]);
      float d20 = __fsub_rn(__fadd_rn(sqi[u], sqj[2*v2+0]), __fmul_rn(2.0f, g0));
      float d21 = __fsub_rn(__fadd_rn(sqi[u], sqj[2*v2+1]), __fmul_rn(2.0f, g1));
      float dd0 = __fdiv_rn(__fsqrt_rn(fmaxf(d20, 0.0f)), sqc);
      float dd1 = __fdiv_rn(__fsqrt_rn(fmaxf(d21, 0.0f)), sqc);
      *(float2*)&Dt[(size_t)row * N1_ + c0] = make_float2(dd0, dd1);
    }
  }
}

// ---------------- 2b) mirror block (128..255, 0..127) from (0..127, 128..255) ----------------
__global__ void mirror_kernel(){
  __shared__ float tile[32][33];
  int t  = blockIdx.z;
  int bx = blockIdx.x * 32;   // col offset inside source block (0..127)
  int by = blockIdx.y * 32;   // row offset inside source block (0..127)
  float* Dt = g_dist1 + (size_t)t * N1_ * N1_;
  int tx = threadIdx.x, ty0 = threadIdx.y;    // 32 x 8
  #pragma unroll
  for (int s = 0; s < 32; s += 8){
    int r = by + ty0 + s;
    tile[ty0 + s][tx] = Dt[(size_t)r * N1_ + 128 + bx + tx];
  }
  __syncthreads();
  #pragma unroll
  for (int s = 0; s < 32; s += 8){
    int c = bx + ty0 + s;
    Dt[(size_t)(128 + c) * N1_ + by + tx] = tile[tx][ty0 + s];
  }
}

// ---------------- 3) knn density + exact threefry noise ----------------
template<int N, int K>
__global__ void knn_kernel(uint32_t key0, uint32_t key1){
  int gid = blockIdx.x * blockDim.x + threadIdx.x;
  if (gid >= T_ * N) return;
  const float* dist = (N == N1_) ? g_dist1 : g_dist2;
  float*       dens = (N == N1_) ? g_dens1 : g_dens2;
  const float* row = dist + (size_t)gid * N;

  float bd[K]; int bix[K];
  #pragma unroll
  for (int p = 0; p < K; p++){ bd[p] = 3.4e38f; bix[p] = 0x7fffffff; }

  for (int j = 0; j < N; j++){
    float d = row[j];
    bool ins = (d < bd[K-1]) || (d == bd[K-1] && j < bix[K-1]);
    if (ins){
      float nd = d; int ni = j;
      #pragma unroll
      for (int p = 0; p < K; p++){
        bool lt = (nd < bd[p]) || (nd == bd[p] && ni < bix[p]);
        if (lt){
          float td = bd[p]; bd[p] = nd; nd = td;
          int   ti = bix[p]; bix[p] = ni; ni = ti;
        }
      }
    }
  }
  float s = 0.f;
  #pragma unroll
  for (int p = 0; p < K; p++) s = __fadd_rn(s, __fmul_rn(bd[p], bd[p]));
  float m = __fdiv_rn(s, (float)K);
  float d = expf(-m);

  const int total = T_ * N, half = total / 2;
  uint32_t o0, o1, u;
  if (gid < half){ threefry2x32(key0, key1, (uint32_t)gid,        (uint32_t)(gid + half), o0, o1); u = o0; }
  else           { threefry2x32(key0, key1, (uint32_t)(gid-half), (uint32_t)gid,          o0, o1); u = o1; }
  float uf = __fadd_rn(__uint_as_float((u >> 9) | 0x3f800000u), -1.0f);
  dens[gid] = __fadd_rn(d, __fmul_rn(uf, 1e-6f));
}

// ---------------- 4) parent_dist, score, top-CN centers, assignment, weights ----------------
template<int N, int CN>
__global__ void cluster_kernel(){
  const int t = blockIdx.x;
  const int i = threadIdx.x;   // blockDim == N
  const float* dist = (N == N1_) ? g_dist1 : g_dist2;
  const float* dens = (N == N1_) ? g_dens1 : g_dens2;
  int*   idxc = (N == N1_) ? g_idx1 : g_idx2;
  float* wout = (N == N1_) ? g_w1   : g_w2;

  __shared__ float sd[N];
  __shared__ float swf[8];
  __shared__ ull   swu[8];
  __shared__ float fbcast;
  __shared__ ull   ubcast;
  __shared__ int sidx[CN];
  __shared__ int scnt[CN];

  const float* D = dist + (size_t)t * N * N;
  sd[i] = dens[t*N + i];
  __syncthreads();

  float di = sd[i];
  const float* rowi = D + (size_t)i * N;
  float minv = 3.4e38f, rmax = 0.f;
  bool hasH = false;
  for (int j = 0; j < N; j += 4){
    float4 d4 = *(const float4*)(rowi + j);
    rmax = fmaxf(rmax, fmaxf(fmaxf(d4.x, d4.y), fmaxf(d4.z, d4.w)));
    if (sd[j+0] > di){ hasH = true; minv = fminf(minv, d4.x); }
    if (sd[j+1] > di){ hasH = true; minv = fminf(minv, d4.y); }
    if (sd[j+2] > di){ hasH = true; minv = fminf(minv, d4.z); }
    if (sd[j+3] > di){ hasH = true; minv = fminf(minv, d4.w); }
  }

  // block max of rmax
  float dmax;
  if (N >= 32){
    float v = rmax;
    #pragma unroll
    for (int o = 16; o; o >>= 1) v = fmaxf(v, __shfl_xor_sync(0xffffffffu, v, o));
    if ((i & 31) == 0) swf[i >> 5] = v;
    __syncthreads();
    if (i < 8){
      float w = swf[i];
      #pragma unroll
      for (int o = 4; o; o >>= 1) w = fmaxf(w, __shfl_xor_sync(0xffu, w, o));
      if (i == 0) fbcast = w;
    }
    __syncthreads();
    dmax = fbcast;
  } else {
    float v = rmax;
    #pragma unroll
    for (int o = 8; o; o >>= 1) v = fmaxf(v, __shfl_xor_sync(0xffffu, v, o));
    if (i == 0) fbcast = v;
    __syncthreads();
    dmax = fbcast;
  }

  float parent = hasH ? minv : dmax;
  float score = __fmul_rn(parent, di);   // score >= 0 -> uint-ordered
  ull key = ((ull)__float_as_uint(score) << 32) | (ull)(0xffffffffu - (uint32_t)i);

  // iterative top-CN by (score desc, index asc) with warp reductions
  for (int c = 0; c < CN; c++){
    ull top;
    if (N >= 32){
      ull v = key;
      #pragma unroll
      for (int o = 16; o; o >>= 1){ ull w = __shfl_xor_sync(0xffffffffu, v, o); if (w > v) v = w; }
      if ((i & 31) == 0) swu[i >> 5] = v;
      __syncthreads();
      if (i < 8){
        ull w = swu[i];
        #pragma unroll
        for (int o = 4; o; o >>= 1){ ull z = __shfl_xor_sync(0xffu, w, o); if (z > w) w = z; }
        if (i == 0) ubcast = w;
      }
      __syncthreads();
      top = ubcast;
    } else {
      ull v = key;
      #pragma unroll
      for (int o = 8; o; o >>= 1){ ull w = __shfl_xor_sync(0xffffu, v, o); if (w > v) v = w; }
      if (i == 0) ubcast = v;
      __syncthreads();
      top = ubcast;
    }
    int widx = (int)(0xffffffffu - (uint32_t)(top & 0xffffffffu));
    if (i == 0) sidx[c] = widx;
    if (i == widx) key = 0ull;
    __syncthreads();
  }

  // assignment: argmin over centers (first occurrence), then center override
  float bv = D[(size_t)sidx[0] * N + i];
  int bc = 0;
  for (int c = 1; c < CN; c++){
    float v = D[(size_t)sidx[c] * N + i];
    if (v < bv){ bv = v; bc = c; }
  }
  for (int c = 0; c < CN; c++) if (sidx[c] == i) bc = c;

  if (i < CN) scnt[i] = 0;
  __syncthreads();
  atomicAdd(&scnt[bc], 1);
  idxc[t*N + i] = bc;
  __syncthreads();
  if (i < CN) wout[t*CN + i] = __fdiv_rn(1.0f, __fadd_rn((float)scnt[i], 1e-6f));
}

// ---------------- 5) scatter-mean merge (scale-then-sum, token order) ----------------
template<int N, int CN>
__global__ void merge_kernel(const float* __restrict__ X){
  int t  = blockIdx.y;
  int ch = blockIdx.x * 128 + threadIdx.x;
  const float* Xp  = (N == N1_) ? X : g_meta1;
  const int*  idxc = (N == N1_) ? g_idx1 : g_idx2;
  const float* w   = (N == N1_) ? g_w1   : g_w2;
  float*      outp = (N == N1_) ? g_meta1 : g_meta2;

  __shared__ int sidx[N];
  __shared__ float sw[CN];
  __shared__ float acc[CN][128];

  for (int n = threadIdx.x; n < N; n += 128) sidx[n] = idxc[t*N + n];
  if (threadIdx.x < CN) sw[threadIdx.x] = w[t*CN + threadIdx.x];
  for (int c = 0; c < CN; c++) acc[c][threadIdx.x] = 0.f;
  __syncthreads();

  const float* Xb = Xp + (size_t)t * N * C_ + ch;
  for (int n = 0; n < N; n++){
    int c = sidx[n];
    float v = __fmul_rn(Xb[(size_t)n * C_], sw[c]);
    acc[c][threadIdx.x] = __fadd_rn(acc[c][threadIdx.x], v);
  }
  for (int c = 0; c < CN; c++)
    outp[((size_t)t * CN + c) * C_ + ch] = acc[c][threadIdx.x];
}

// ---------------- 6) layer-2 Gram + distance (16x16 per batch) ----------------
__global__ void gram2_kernel(){
  int t = blockIdx.x;
  int tid = threadIdx.x;           // 256 = 16x16
  int i = tid >> 4, j = tid & 15;
  __shared__ float chunk[N2_][89];
  __shared__ float G[N2_][N2_ + 1];
  const float* Mb = g_meta1 + (size_t)t * N2_ * C_;
  float dot = 0.f;
  for (int c0 = 0; c0 < C_; c0 += 88){
    for (int e = tid; e < N2_ * 88; e += 256){
      int r = e / 88, cc = e - r * 88;
      chunk[r][cc] = Mb[(size_t)r * C_ + c0 + cc];
    }
    __syncthreads();
    #pragma unroll 8
    for (int k = 0; k < 88; k++) dot = __fmaf_rn(chunk[i][k], chunk[j][k], dot);
    __syncthreads();
  }
  G[i][j] = dot;
  __syncthreads();
  float s  = __fadd_rn(G[i][i], G[j][j]);
  float d2 = __fsub_rn(s, __fmul_rn(2.0f, dot));
  g_dist2[(t*N2_ + i)*N2_ + j] = __fdiv_rn(__fsqrt_rn(fmaxf(d2, 0.0f)), __fsqrt_rn((float)C_));
}

// ---------------- 7) modulation (softmax) + grouping order ----------------
__global__ void modu_kernel(const float* __restrict__ sw_, const float* __restrict__ sb_){
  int t = blockIdx.x;
  int tid = threadIdx.x;        // 192
  int wp = tid >> 5, lane = tid & 31;
  __shared__ float smean[CN2_];
  if (wp < CN2_){
    const float* row = g_meta2 + ((size_t)t * CN2_ + wp) * C_;
    float s = 0.f;
    for (int c = lane; c < C_; c += 32) s = __fadd_rn(s, row[c]);
    #pragma unroll
    for (int o = 16; o; o >>= 1) s = __fadd_rn(s, __shfl_down_sync(0xffffffffu, s, o));
    if (lane == 0) smean[wp] = __fdiv_rn(s, (float)C_);
  }
  __syncthreads();
  if (tid == 0){
    float logit[CN2_], e[CN2_];
    for (int k = 0; k < CN2_; k++){
      float l = 0.f;
      for (int j = 0; j < CN2_; j++) l = __fmaf_rn(smean[j], sw_[k*CN2_ + j], l);
      logit[k] = __fadd_rn(l, sb_[k]);
    }
    float mx = logit[0];
    for (int k = 1; k < CN2_; k++) mx = fmaxf(mx, logit[k]);
    float ssum = 0.f;
    for (int k = 0; k < CN2_; k++){ e[k] = expf(__fsub_rn(logit[k], mx)); ssum = __fadd_rn(ssum, e[k]); }
    for (int k = 0; k < CN2_; k++) g_modu[t*CN2_ + k] = __fdiv_rn(e[k], ssum);

    int key[OT_], src[OT_];
    for (int v = 0; v < CN2_; v++){ key[v] = v * 18; src[v] = v; }
    for (int n = 0; n < CN1_; n++){
      key[CN2_ + n] = g_idx2[t*CN1_ + n] * 18 + 1 + n;
      src[CN2_ + n] = CN2_ + n;
    }
    for (int a = 1; a < OT_; a++){
      int ka = key[a], sa = src[a], b = a - 1;
      while (b >= 0 && key[b] > ka){ key[b+1] = key[b]; src[b+1] = src[b]; b--; }
      key[b+1] = ka; src[b+1] = sa;
    }
    for (int p = 0; p < OT_; p++){
      g_src [t*OT_ + p] = src[p];
      g_cidv[t*OT_ + p] = key[p] / 18;
    }
  }
}

// ---------------- 8) emit scaled grouped tokens ----------------
__global__ void emit_kernel(float* __restrict__ out){
  int t  = blockIdx.y;
  int ch = blockIdx.x * 128 + threadIdx.x;
  __shared__ int ssrc[OT_], scid[OT_];
  __shared__ float sm[CN2_];
  if (threadIdx.x < OT_){
    ssrc[threadIdx.x] = g_src [t*OT_ + threadIdx.x];
    scid[threadIdx.x] = g_cidv[t*OT_ + threadIdx.x];
  }
  if (threadIdx.x < CN2_) sm[threadIdx.x] = g_modu[t*CN2_ + threadIdx.x];
  __syncthreads();
  for (int p = 0; p < OT_; p++){
    int s = ssrc[p];
    float v = (s < CN2_) ? g_meta2[((size_t)t*CN2_ + s) * C_ + ch]
                         : g_meta1[((size_t)t*CN1_ + (s - CN2_)) * C_ + ch];
    out[((size_t)t*OT_ + p) * C_ + ch] = __fmul_rn(v, sm[scid[p]]);
  }
}

// ---------------- launch ----------------
extern "C" void kernel_launch(void* const* d_in, const int* in_sizes, int n_in,
                              void* d_out, int out_size){
  (void)in_sizes; (void)n_in; (void)out_size;
  const float* vis = (const float*)d_in[0];
  const float* sw  = (const float*)d_in[1];
  const float* sb  = (const float*)d_in[2];
  float* out = (float*)d_out;

  uint32_t a0, b0, a1, b1;
  threefry2x32(0u, 42u, 0u, 2u, a0, b0);
  threefry2x32(0u, 42u, 1u, 3u, a1, b1);

  sq_kernel<<<T_*N1_/8, 256>>>(vis);
  gram1_kernel<<<dim3(3, T_), 256>>>(vis);
  mirror_kernel<<<dim3(4, 4, T_), dim3(32, 8)>>>();
  knn_kernel<N1_, K1_><<<(T_*N1_)/256, 256>>>(a0, a1);
  cluster_kernel<N1_, CN1_><<<T_, N1_>>>();
  merge_kernel<N1_, CN1_><<<dim3(C_/128, T_), 128>>>(vis);
  gram2_kernel<<<T_, 256>>>();
  knn_kernel<N2_, K2_><<<(T_*N2_)/256, 256>>>(b0, b1);
  cluster_kernel<N2_, CN2_><<<T_, N2_>>>();
  merge_kernel<N2_, CN2_><<<dim3(C_/128, T_), 128>>>(nullptr);
  modu_kernel<<<T_, 192>>>(sw, sb);
  emit_kernel<<<dim3(C_/128, T_), 128>>>(out);
}

// round 5
// speedup vs baseline: 1.5523x; 1.4427x over previous
#include <cuda_runtime.h>
#include <stdint.h>
#include <math.h>

#define T_   128
#define N1_  256
#define C_   1408
#define K1_  8
#define CN1_ 16
#define N2_  16
#define K2_  3
#define CN2_ 6
#define OT_  22

typedef unsigned long long ull;

// ---------------- scratch (static __device__, no runtime allocation) ----------------
static __device__ float g_dist1[(size_t)T_*N1_*N1_];   // 33.5 MB
static __device__ float g_sq1  [T_*N1_];
static __device__ float g_dens1[T_*N1_];
static __device__ int   g_idx1 [T_*N1_];
static __device__ float g_w1   [T_*CN1_];
static __device__ float g_meta1[(size_t)T_*CN1_*C_];   // 11.5 MB
static __device__ float g_dist2[T_*N2_*N2_];
static __device__ float g_dens2[T_*N2_];
static __device__ int   g_idx2 [T_*N2_];
static __device__ float g_w2   [T_*CN2_];
static __device__ float g_meta2[(size_t)T_*CN2_*C_];   // 4.3 MB
static __device__ float g_modu [T_*CN2_];
static __device__ int   g_src  [T_*OT_];
static __device__ int   g_cidv [T_*OT_];

// ---------------- threefry2x32 (exact JAX replica) ----------------
__host__ __device__ __forceinline__ uint32_t rotl32(uint32_t v, int r){ return (v<<r)|(v>>(32-r)); }

__host__ __device__ __forceinline__ void threefry2x32(uint32_t ks0, uint32_t ks1,
                                                      uint32_t x0, uint32_t x1,
                                                      uint32_t& o0, uint32_t& o1){
  uint32_t ks2 = ks0 ^ ks1 ^ 0x1BD11BDAu;
  x0 += ks0; x1 += ks1;
  x0+=x1; x1=rotl32(x1,13); x1^=x0;
  x0+=x1; x1=rotl32(x1,15); x1^=x0;
  x0+=x1; x1=rotl32(x1,26); x1^=x0;
  x0+=x1; x1=rotl32(x1, 6); x1^=x0;
  x0+=ks1; x1+=ks2+1u;
  x0+=x1; x1=rotl32(x1,17); x1^=x0;
  x0+=x1; x1=rotl32(x1,29); x1^=x0;
  x0+=x1; x1=rotl32(x1,16); x1^=x0;
  x0+=x1; x1=rotl32(x1,24); x1^=x0;
  x0+=ks2; x1+=ks0+2u;
  x0+=x1; x1=rotl32(x1,13); x1^=x0;
  x0+=x1; x1=rotl32(x1,15); x1^=x0;
  x0+=x1; x1=rotl32(x1,26); x1^=x0;
  x0+=x1; x1=rotl32(x1, 6); x1^=x0;
  x0+=ks0; x1+=ks1+3u;
  x0+=x1; x1=rotl32(x1,17); x1^=x0;
  x0+=x1; x1=rotl32(x1,29); x1^=x0;
  x0+=x1; x1=rotl32(x1,16); x1^=x0;
  x0+=x1; x1=rotl32(x1,24); x1^=x0;
  x0+=ks1; x1+=ks2+4u;
  o0 = x0; o1 = x1;
}

// packed dual-f32 FMA (SASS: FFMA2) — bitwise identical to two scalar __fmaf_rn
__device__ __forceinline__ ull ffma2(ull a, ull b, ull c){
  ull d;
  asm("fma.rn.f32x2 %0, %1, %2, %3;" : "=l"(d) : "l"(a), "l"(b), "l"(c));
  return d;
}
__device__ __forceinline__ ull dup2(float a){
  ull d;
  asm("mov.b64 %0, {%1, %1};" : "=l"(d) : "f"(a));
  return d;
}
__device__ __forceinline__ float lo32(ull v){ return __uint_as_float((uint32_t)v); }
__device__ __forceinline__ float hi32(ull v){ return __uint_as_float((uint32_t)(v >> 32)); }

// bank-swizzle: float offset within one 128-float k-row for logical column c.
// chunk = c>>2 (16B), group = chunk>>3, slot = (chunk&7) ^ (group&1); k adds XOR of
// ((k>>2)&3)<<1 on slot, i.e. ((k>>2)&3)<<3 on the float offset.
__device__ __forceinline__ int swbase(int c){
  int ch = c >> 2, g = ch >> 3, sl = (ch & 7) ^ (g & 1);
  return (((g << 3) | sl) << 2) | (c & 3);
}

// ---------------- 1) per-row squared norm ----------------
__global__ void sq_kernel(const float* __restrict__ X){
  int row  = blockIdx.x * 8 + (threadIdx.x >> 5);
  int lane = threadIdx.x & 31;
  const float* xr = X + (size_t)row * C_;
  float s = 0.f;
  for (int c = lane; c < C_; c += 32){
    float v = xr[c];
    s = __fadd_rn(s, __fmul_rn(v, v));
  }
  #pragma unroll
  for (int o = 16; o; o >>= 1) s = __fadd_rn(s, __shfl_down_sync(0xffffffffu, s, o));
  if (lane == 0) g_sq1[row] = s;
}

// ---------------- 2) Gram + distance (layer 1) ----------------
// FFMA2, swizzled smem (conflict-free reads AND writes), register-packed A-dup,
// double-buffered with register prefetch. blockIdx.x: 0->(0,0) 1->(128,128) 2->(0,128).
__global__ void __launch_bounds__(256,2) gram1_kernel(const float* __restrict__ X){
  int t  = blockIdx.y;
  int bb = blockIdx.x;
  int bi = (bb == 1) ? 128 : 0;
  int bj = (bb == 0) ? 0   : 128;
  const float* Xb = X + (size_t)t * N1_ * C_;

  __shared__ float As[2][16*128];
  __shared__ float Bs[2][16*128];

  int tid = threadIdx.x;
  int tx = tid & 15, ty = tid >> 4;
  int r  = tid >> 2;             // 0..63 (also r+64)
  int lc = (tid & 3) << 2;       // k-subcolumns 0,4,8,12
  int lcg = lc >> 2;             // kg for the 4 k-rows this thread writes

  // writer offsets (k-row kk=lc+q -> (lc+q)*128 + wX)
  int wA0 = swbase(r)      ^ (lcg << 3);
  int wA1 = swbase(r + 64) ^ (lcg << 3);

  // reader bases (XOR ((k>>2)&3)<<3 applied per k)
  int bA0 = swbase(ty * 8),     bA1 = swbase(ty * 8 + 4);
  int bB0 = swbase(tx * 8),     bB1 = swbase(tx * 8 + 4);

  ull acc[8][4];
  #pragma unroll
  for (int u = 0; u < 8; u++)
    #pragma unroll
    for (int v = 0; v < 4; v++) acc[u][v] = 0ull;

  const float* srcA0 = Xb + (size_t)(bi + r)      * C_ + lc;
  const float* srcA1 = Xb + (size_t)(bi + r + 64) * C_ + lc;
  const float* srcB0 = Xb + (size_t)(bj + r)      * C_ + lc;
  const float* srcB1 = Xb + (size_t)(bj + r + 64) * C_ + lc;

  const int NIT = C_ / 16;   // 88

  // prologue: chunk 0
  float4 pa0 = *(const float4*)(srcA0);
  float4 pa1 = *(const float4*)(srcA1);
  float4 pb0 = *(const float4*)(srcB0);
  float4 pb1 = *(const float4*)(srcB1);
  {
    float* A = As[0]; float* B = Bs[0];
    A[(lc+0)*128 + wA0] = pa0.x; A[(lc+1)*128 + wA0] = pa0.y;
    A[(lc+2)*128 + wA0] = pa0.z; A[(lc+3)*128 + wA0] = pa0.w;
    A[(lc+0)*128 + wA1] = pa1.x; A[(lc+1)*128 + wA1] = pa1.y;
    A[(lc+2)*128 + wA1] = pa1.z; A[(lc+3)*128 + wA1] = pa1.w;
    B[(lc+0)*128 + wA0] = pb0.x; B[(lc+1)*128 + wA0] = pb0.y;
    B[(lc+2)*128 + wA0] = pb0.z; B[(lc+3)*128 + wA0] = pb0.w;
    B[(lc+0)*128 + wA1] = pb1.x; B[(lc+1)*128 + wA1] = pb1.y;
    B[(lc+2)*128 + wA1] = pb1.z; B[(lc+3)*128 + wA1] = pb1.w;
  }
  __syncthreads();

  int buf = 0;
  for (int it = 0; it < NIT; it++){
    bool more = (it + 1 < NIT);
    int koff = (it + 1) * 16;
    if (more){
      pa0 = *(const float4*)(srcA0 + koff);
      pa1 = *(const float4*)(srcA1 + koff);
      pb0 = *(const float4*)(srcB0 + koff);
      pb1 = *(const float4*)(srcB1 + koff);
    }
    const float* A = As[buf];
    const float* B = Bs[buf];
    #pragma unroll
    for (int k = 0; k < 16; k++){
      int kx = ((k >> 2) & 3) << 3;
      const float* Ak = A + k * 128;
      const float* Bk = B + k * 128;
      float4 a0 = *(const float4*)(Ak + (bA0 ^ kx));
      float4 a1 = *(const float4*)(Ak + (bA1 ^ kx));
      ulonglong2 u0 = *(const ulonglong2*)(Bk + (bB0 ^ kx));
      ulonglong2 u1 = *(const ulonglong2*)(Bk + (bB1 ^ kx));
      ull bv0 = u0.x, bv1 = u0.y, bv2 = u1.x, bv3 = u1.y;
      float af[8] = {a0.x, a0.y, a0.z, a0.w, a1.x, a1.y, a1.z, a1.w};
      #pragma unroll
      for (int u = 0; u < 8; u++){
        ull ad = dup2(af[u]);
        acc[u][0] = ffma2(ad, bv0, acc[u][0]);
        acc[u][1] = ffma2(ad, bv1, acc[u][1]);
        acc[u][2] = ffma2(ad, bv2, acc[u][2]);
        acc[u][3] = ffma2(ad, bv3, acc[u][3]);
      }
    }
    if (more){
      float* An = As[buf ^ 1]; float* Bn = Bs[buf ^ 1];
      An[(lc+0)*128 + wA0] = pa0.x; An[(lc+1)*128 + wA0] = pa0.y;
      An[(lc+2)*128 + wA0] = pa0.z; An[(lc+3)*128 + wA0] = pa0.w;
      An[(lc+0)*128 + wA1] = pa1.x; An[(lc+1)*128 + wA1] = pa1.y;
      An[(lc+2)*128 + wA1] = pa1.z; An[(lc+3)*128 + wA1] = pa1.w;
      Bn[(lc+0)*128 + wA0] = pb0.x; Bn[(lc+1)*128 + wA0] = pb0.y;
      Bn[(lc+2)*128 + wA0] = pb0.z; Bn[(lc+3)*128 + wA0] = pb0.w;
      Bn[(lc+0)*128 + wA1] = pb1.x; Bn[(lc+1)*128 + wA1] = pb1.y;
      Bn[(lc+2)*128 + wA1] = pb1.z; Bn[(lc+3)*128 + wA1] = pb1.w;
    }
    __syncthreads();
    buf ^= 1;
  }

  float sqi[8], sqj[8];
  #pragma unroll
  for (int u = 0; u < 8; u++){
    sqi[u] = g_sq1[t*N1_ + bi + (ty<<3) + u];
    sqj[u] = g_sq1[t*N1_ + bj + (tx<<3) + u];
  }
  float sqc = __fsqrt_rn((float)C_);
  float* Dt = g_dist1 + (size_t)t * N1_ * N1_;
  #pragma unroll
  for (int u = 0; u < 8; u++){
    int row = bi + (ty<<3) + u;
    #pragma unroll
    for (int v2 = 0; v2 < 4; v2++){
      int c0 = bj + (tx<<3) + 2*v2;
      float g0 = lo32(acc[u][v2]), g1 = hi32(acc[u][v2]);
      float d20 = __fsub_rn(__fadd_rn(sqi[u], sqj[2*v2+0]), __fmul_rn(2.0f, g0));
      float d21 = __fsub_rn(__fadd_rn(sqi[u], sqj[2*v2+1]), __fmul_rn(2.0f, g1));
      float dd0 = __fdiv_rn(__fsqrt_rn(fmaxf(d20, 0.0f)), sqc);
      float dd1 = __fdiv_rn(__fsqrt_rn(fmaxf(d21, 0.0f)), sqc);
      *(float2*)&Dt[(size_t)row * N1_ + c0] = make_float2(dd0, dd1);
    }
  }
}

// ---------------- 2b) mirror block (128..255, 0..127) from (0..127, 128..255) ----------------
__global__ void mirror_kernel(){
  __shared__ float tile[32][33];
  int t  = blockIdx.z;
  int bx = blockIdx.x * 32;
  int by = blockIdx.y * 32;
  float* Dt = g_dist1 + (size_t)t * N1_ * N1_;
  int tx = threadIdx.x, ty0 = threadIdx.y;    // 32 x 8
  #pragma unroll
  for (int s = 0; s < 32; s += 8){
    int r = by + ty0 + s;
    tile[ty0 + s][tx] = Dt[(size_t)r * N1_ + 128 + bx + tx];
  }
  __syncthreads();
  #pragma unroll
  for (int s = 0; s < 32; s += 8){
    int c = bx + ty0 + s;
    Dt[(size_t)(128 + c) * N1_ + by + tx] = tile[tx][ty0 + s];
  }
}

// ---------------- 3a) knn layer-1: warp per row, coalesced, u64-key extraction ----------------
__global__ void knn1_kernel(uint32_t key0, uint32_t key1){
  int w    = (blockIdx.x * blockDim.x + threadIdx.x) >> 5;   // row id 0..32767
  int lane = threadIdx.x & 31;
  const float* row = g_dist1 + (size_t)w * N1_;

  ull kk[8];
  #pragma unroll
  for (int p = 0; p < 8; p++){
    int j = lane + 32 * p;
    float d = row[j];
    kk[p] = ((ull)__float_as_uint(d) << 32) | (uint32_t)j;
  }

  float s = 0.f;
  #pragma unroll
  for (int rdy = 0; rdy < K1_; rdy++){
    ull m = kk[0];
    #pragma unroll
    for (int p = 1; p < 8; p++) if (kk[p] < m) m = kk[p];
    #pragma unroll
    for (int o = 16; o; o >>= 1){ ull z = __shfl_xor_sync(0xffffffffu, m, o); if (z < m) m = z; }
    float d = __uint_as_float((uint32_t)(m >> 32));
    s = __fadd_rn(s, __fmul_rn(d, d));
    #pragma unroll
    for (int p = 0; p < 8; p++) if (kk[p] == m) kk[p] = ~0ull;
  }

  if (lane == 0){
    float mean = __fdiv_rn(s, (float)K1_);
    float dens = expf(-mean);
    const int total = T_ * N1_, half = total / 2;
    int gid = w;
    uint32_t o0, o1, u;
    if (gid < half){ threefry2x32(key0, key1, (uint32_t)gid,        (uint32_t)(gid + half), o0, o1); u = o0; }
    else           { threefry2x32(key0, key1, (uint32_t)(gid-half), (uint32_t)gid,          o0, o1); u = o1; }
    float uf = __fadd_rn(__uint_as_float((u >> 9) | 0x3f800000u), -1.0f);
    g_dens1[gid] = __fadd_rn(dens, __fmul_rn(uf, 1e-6f));
  }
}

// ---------------- 3b) knn layer-2 (tiny, per-thread) ----------------
template<int N, int K>
__global__ void knn_kernel(uint32_t key0, uint32_t key1){
  int gid = blockIdx.x * blockDim.x + threadIdx.x;
  if (gid >= T_ * N) return;
  const float* row = g_dist2 + (size_t)gid * N;

  float bd[K]; int bix[K];
  #pragma unroll
  for (int p = 0; p < K; p++){ bd[p] = 3.4e38f; bix[p] = 0x7fffffff; }

  for (int j = 0; j < N; j++){
    float d = row[j];
    bool ins = (d < bd[K-1]) || (d == bd[K-1] && j < bix[K-1]);
    if (ins){
      float nd = d; int ni = j;
      #pragma unroll
      for (int p = 0; p < K; p++){
        bool lt = (nd < bd[p]) || (nd == bd[p] && ni < bix[p]);
        if (lt){
          float td = bd[p]; bd[p] = nd; nd = td;
          int   ti = bix[p]; bix[p] = ni; ni = ti;
        }
      }
    }
  }
  float s = 0.f;
  #pragma unroll
  for (int p = 0; p < K; p++) s = __fadd_rn(s, __fmul_rn(bd[p], bd[p]));
  float m = __fdiv_rn(s, (float)K);
  float d = expf(-m);

  const int total = T_ * N, half = total / 2;
  uint32_t o0, o1, u;
  if (gid < half){ threefry2x32(key0, key1, (uint32_t)gid,        (uint32_t)(gid + half), o0, o1); u = o0; }
  else           { threefry2x32(key0, key1, (uint32_t)(gid-half), (uint32_t)gid,          o0, o1); u = o1; }
  float uf = __fadd_rn(__uint_as_float((u >> 9) | 0x3f800000u), -1.0f);
  g_dens2[gid] = __fadd_rn(d, __fmul_rn(uf, 1e-6f));
}

// ---------------- 4) parent_dist, score, top-CN centers, assignment, weights ----------------
// column-major scan: D[j*N+i] == D[i*N+j] (matrix is symmetric) -> coalesced.
template<int N, int CN>
__global__ void cluster_kernel(){
  const int t = blockIdx.x;
  const int i = threadIdx.x;   // blockDim == N
  const float* dist = (N == N1_) ? g_dist1 : g_dist2;
  const float* dens = (N == N1_) ? g_dens1 : g_dens2;
  int*   idxc = (N == N1_) ? g_idx1 : g_idx2;
  float* wout = (N == N1_) ? g_w1   : g_w2;

  __shared__ float sd[N];
  __shared__ float swf[8];
  __shared__ ull   swu[8];
  __shared__ float fbcast;
  __shared__ ull   ubcast;
  __shared__ int sidx[CN];
  __shared__ int scnt[CN];

  const float* D = dist + (size_t)t * N * N;
  sd[i] = dens[t*N + i];
  __syncthreads();

  float di = sd[i];
  const float* Dc = D + i;
  float minv = 3.4e38f, rmax = 0.f;
  bool hasH = false;
  #pragma unroll 8
  for (int j = 0; j < N; j++){
    float dv = Dc[(size_t)j * N];
    rmax = fmaxf(rmax, dv);
    if (sd[j] > di){ hasH = true; minv = fminf(minv, dv); }
  }

  // block max of rmax
  float dmax;
  if (N >= 32){
    float v = rmax;
    #pragma unroll
    for (int o = 16; o; o >>= 1) v = fmaxf(v, __shfl_xor_sync(0xffffffffu, v, o));
    if ((i & 31) == 0) swf[i >> 5] = v;
    __syncthreads();
    if (i < 8){
      float z = swf[i];
      #pragma unroll
      for (int o = 4; o; o >>= 1) z = fmaxf(z, __shfl_xor_sync(0xffu, z, o));
      if (i == 0) fbcast = z;
    }
    __syncthreads();
    dmax = fbcast;
  } else {
    float v = rmax;
    #pragma unroll
    for (int o = 8; o; o >>= 1) v = fmaxf(v, __shfl_xor_sync(0xffffu, v, o));
    if (i == 0) fbcast = v;
    __syncthreads();
    dmax = fbcast;
  }

  float parent = hasH ? minv : dmax;
  float score = __fmul_rn(parent, di);
  ull key = ((ull)__float_as_uint(score) << 32) | (ull)(0xffffffffu - (uint32_t)i);

  for (int c = 0; c < CN; c++){
    ull top;
    if (N >= 32){
      ull v = key;
      #pragma unroll
      for (int o = 16; o; o >>= 1){ ull z = __shfl_xor_sync(0xffffffffu, v, o); if (z > v) v = z; }
      if ((i & 31) == 0) swu[i >> 5] = v;
      __syncthreads();
      if (i < 8){
        ull z = swu[i];
        #pragma unroll
        for (int o = 4; o; o >>= 1){ ull y = __shfl_xor_sync(0xffu, z, o); if (y > z) z = y; }
        if (i == 0) ubcast = z;
      }
      __syncthreads();
      top = ubcast;
    } else {
      ull v = key;
      #pragma unroll
      for (int o = 8; o; o >>= 1){ ull z = __shfl_xor_sync(0xffffu, v, o); if (z > v) v = z; }
      if (i == 0) ubcast = v;
      __syncthreads();
      top = ubcast;
    }
    int widx = (int)(0xffffffffu - (uint32_t)(top & 0xffffffffu));
    if (i == 0) sidx[c] = widx;
    if (i == widx) key = 0ull;
    __syncthreads();
  }

  float bv = D[(size_t)sidx[0] * N + i];
  int bc = 0;
  for (int c = 1; c < CN; c++){
    float v = D[(size_t)sidx[c] * N + i];
    if (v < bv){ bv = v; bc = c; }
  }
  for (int c = 0; c < CN; c++) if (sidx[c] == i) bc = c;

  if (i < CN) scnt[i] = 0;
  __syncthreads();
  atomicAdd(&scnt[bc], 1);
  idxc[t*N + i] = bc;
  __syncthreads();
  if (i < CN) wout[t*CN + i] = __fdiv_rn(1.0f, __fadd_rn((float)scnt[i], 1e-6f));
}

// ---------------- 5) scatter-mean merge ----------------
template<int N, int CN>
__global__ void merge_kernel(const float* __restrict__ X){
  int t  = blockIdx.y;
  int ch = blockIdx.x * 128 + threadIdx.x;
  const float* Xp  = (N == N1_) ? X : g_meta1;
  const int*  idxc = (N == N1_) ? g_idx1 : g_idx2;
  const float* w   = (N == N1_) ? g_w1   : g_w2;
  float*      outp = (N == N1_) ? g_meta1 : g_meta2;

  __shared__ int sidx[N];
  __shared__ float sw[CN];
  __shared__ float acc[CN][128];

  for (int n = threadIdx.x; n < N; n += 128) sidx[n] = idxc[t*N + n];
  if (threadIdx.x < CN) sw[threadIdx.x] = w[t*CN + threadIdx.x];
  for (int c = 0; c < CN; c++) acc[c][threadIdx.x] = 0.f;
  __syncthreads();

  const float* Xb = Xp + (size_t)t * N * C_ + ch;
  for (int n = 0; n < N; n++){
    int c = sidx[n];
    float v = __fmul_rn(Xb[(size_t)n * C_], sw[c]);
    acc[c][threadIdx.x] = __fadd_rn(acc[c][threadIdx.x], v);
  }
  for (int c = 0; c < CN; c++)
    outp[((size_t)t * CN + c) * C_ + ch] = acc[c][threadIdx.x];
}

// ---------------- 6) layer-2 Gram + distance ----------------
__global__ void gram2_kernel(){
  int t = blockIdx.x;
  int tid = threadIdx.x;           // 256 = 16x16
  int i = tid >> 4, j = tid & 15;
  __shared__ float chunk[N2_][89];
  __shared__ float G[N2_][N2_ + 1];
  const float* Mb = g_meta1 + (size_t)t * N2_ * C_;
  float dot = 0.f;
  for (int c0 = 0; c0 < C_; c0 += 88){
    for (int e = tid; e < N2_ * 88; e += 256){
      int r = e / 88, cc = e - r * 88;
      chunk[r][cc] = Mb[(size_t)r * C_ + c0 + cc];
    }
    __syncthreads();
    #pragma unroll 8
    for (int k = 0; k < 88; k++) dot = __fmaf_rn(chunk[i][k], chunk[j][k], dot);
    __syncthreads();
  }
  G[i][j] = dot;
  __syncthreads();
  float s  = __fadd_rn(G[i][i], G[j][j]);
  float d2 = __fsub_rn(s, __fmul_rn(2.0f, dot));
  g_dist2[(t*N2_ + i)*N2_ + j] = __fdiv_rn(__fsqrt_rn(fmaxf(d2, 0.0f)), __fsqrt_rn((float)C_));
}

// ---------------- 7) modulation (softmax) + grouping order ----------------
__global__ void modu_kernel(const float* __restrict__ sw_, const float* __restrict__ sb_){
  int t = blockIdx.x;
  int tid = threadIdx.x;        // 192
  int wp = tid >> 5, lane = tid & 31;
  __shared__ float smean[CN2_];
  if (wp < CN2_){
    const float* row = g_meta2 + ((size_t)t * CN2_ + wp) * C_;
    float s = 0.f;
    for (int c = lane; c < C_; c += 32) s = __fadd_rn(s, row[c]);
    #pragma unroll
    for (int o = 16; o; o >>= 1) s = __fadd_rn(s, __shfl_down_sync(0xffffffffu, s, o));
    if (lane == 0) smean[wp] = __fdiv_rn(s, (float)C_);
  }
  __syncthreads();
  if (tid == 0){
    float logit[CN2_], e[CN2_];
    for (int k = 0; k < CN2_; k++){
      float l = 0.f;
      for (int j = 0; j < CN2_; j++) l = __fmaf_rn(smean[j], sw_[k*CN2_ + j], l);
      logit[k] = __fadd_rn(l, sb_[k]);
    }
    float mx = logit[0];
    for (int k = 1; k < CN2_; k++) mx = fmaxf(mx, logit[k]);
    float ssum = 0.f;
    for (int k = 0; k < CN2_; k++){ e[k] = expf(__fsub_rn(logit[k], mx)); ssum = __fadd_rn(ssum, e[k]); }
    for (int k = 0; k < CN2_; k++) g_modu[t*CN2_ + k] = __fdiv_rn(e[k], ssum);

    int key[OT_], src[OT_];
    for (int v = 0; v < CN2_; v++){ key[v] = v * 18; src[v] = v; }
    for (int n = 0; n < CN1_; n++){
      key[CN2_ + n] = g_idx2[t*CN1_ + n] * 18 + 1 + n;
      src[CN2_ + n] = CN2_ + n;
    }
    for (int a = 1; a < OT_; a++){
      int ka = key[a], sa = src[a], b = a - 1;
      while (b >= 0 && key[b] > ka){ key[b+1] = key[b]; src[b+1] = src[b]; b--; }
      key[b+1] = ka; src[b+1] = sa;
    }
    for (int p = 0; p < OT_; p++){
      g_src [t*OT_ + p] = src[p];
      g_cidv[t*OT_ + p] = key[p] / 18;
    }
  }
}

// ---------------- 8) emit scaled grouped tokens ----------------
__global__ void emit_kernel(float* __restrict__ out){
  int t  = blockIdx.y;
  int ch = blockIdx.x * 128 + threadIdx.x;
  __shared__ int ssrc[OT_], scid[OT_];
  __shared__ float sm[CN2_];
  if (threadIdx.x < OT_){
    ssrc[threadIdx.x] = g_src [t*OT_ + threadIdx.x];
    scid[threadIdx.x] = g_cidv[t*OT_ + threadIdx.x];
  }
  if (threadIdx.x < CN2_) sm[threadIdx.x] = g_modu[t*CN2_ + threadIdx.x];
  __syncthreads();
  for (int p = 0; p < OT_; p++){
    int s = ssrc[p];
    float v = (s < CN2_) ? g_meta2[((size_t)t*CN2_ + s) * C_ + ch]
                         : g_meta1[((size_t)t*CN1_ + (s - CN2_)) * C_ + ch];
    out[((size_t)t*OT_ + p) * C_ + ch] = __fmul_rn(v, sm[scid[p]]);
  }
}

// ---------------- launch ----------------
extern "C" void kernel_launch(void* const* d_in, const int* in_sizes, int n_in,
                              void* d_out, int out_size){
  (void)in_sizes; (void)n_in; (void)out_size;
  const float* vis = (const float*)d_in[0];
  const float* sw  = (const float*)d_in[1];
  const float* sb  = (const float*)d_in[2];
  float* out = (float*)d_out;

  uint32_t a0, b0, a1, b1;
  threefry2x32(0u, 42u, 0u, 2u, a0, b0);
  threefry2x32(0u, 42u, 1u, 3u, a1, b1);

  sq_kernel<<<T_*N1_/8, 256>>>(vis);
  gram1_kernel<<<dim3(3, T_), 256>>>(vis);
  mirror_kernel<<<dim3(4, 4, T_), dim3(32, 8)>>>();
  knn1_kernel<<<(T_*N1_*32)/256, 256>>>(a0, a1);
  cluster_kernel<N1_, CN1_><<<T_, N1_>>>();
  merge_kernel<N1_, CN1_><<<dim3(C_/128, T_), 128>>>(vis);
  gram2_kernel<<<T_, 256>>>();
  knn_kernel<N2_, K2_><<<(T_*N2_)/256, 256>>>(b0, b1);
  cluster_kernel<N2_, CN2_><<<T_, N2_>>>();
  merge_kernel<N2_, CN2_><<<dim3(C_/128, T_), 128>>>(nullptr);
  modu_kernel<<<T_, 192>>>(sw, sb);
  emit_kernel<<<dim3(C_/128, T_), 128>>>(out);
}